// round 1
// baseline (speedup 1.0000x reference)
#include <cuda_runtime.h>

#define BB   64
#define CC   64
#define TT   128
#define VV   25
#define RR   8
#define TSN  9
#define OUTC 64
#define TV   (TT*VV)      // 3200
#define XPAD (TT+TSN-1)   // 136

// ---- device scratch (allocation-free contract: __device__ globals) ----
__device__ float g_xm[BB*CC*VV];          // time-mean of x        (400 KB)
__device__ float g_rel[BB*RR*VV*VV];      // tanh relation         (1.28 MB)
__device__ float g_z[BB*CC*TT*VV];        // intermediate z        (52.4 MB)

// ============================================================
// K1: xm[b,c,v] = mean_t x[b,c,t,v]
// ============================================================
__global__ void k1_mean(const float* __restrict__ x) {
    int bc = blockIdx.x;            // b*CC + c
    int v  = threadIdx.x;
    if (v >= VV) return;
    const float* p = x + bc * TV + v;
    float acc = 0.f;
#pragma unroll 8
    for (int t = 0; t < TT; ++t) acc += p[t*VV];
    g_xm[bc*VV + v] = acc * (1.0f / TT);
}

// ============================================================
// K2: x1/x2 = W·xm + b ; rel[b,r,v,j] = tanh(x1[r,v] - x2[r,j])
// ============================================================
__global__ void k2_rel(const float* __restrict__ W1, const float* __restrict__ b1,
                       const float* __restrict__ W2, const float* __restrict__ b2) {
    int b   = blockIdx.x;
    int tid = threadIdx.x;
    __shared__ float s_xm[CC*VV];   // 1600
    __shared__ float s_x1[RR*VV];
    __shared__ float s_x2[RR*VV];

    for (int i = tid; i < CC*VV; i += blockDim.x) s_xm[i] = g_xm[b*CC*VV + i];
    __syncthreads();

    for (int i = tid; i < RR*VV; i += blockDim.x) {
        int r = i / VV, v = i % VV;
        float a1 = b1[r], a2 = b2[r];
#pragma unroll 8
        for (int c = 0; c < CC; ++c) {
            float xv = s_xm[c*VV + v];
            a1 += W1[r*CC + c] * xv;
            a2 += W2[r*CC + c] * xv;
        }
        s_x1[i] = a1; s_x2[i] = a2;
    }
    __syncthreads();

    for (int i = tid; i < RR*VV*VV; i += blockDim.x) {
        int r   = i / (VV*VV);
        int rem = i % (VV*VV);
        int v   = rem / VV;
        int j   = rem % VV;
        g_rel[b*RR*VV*VV + i] = tanhf(s_x1[r*VV + v] - s_x2[r*VV + j]);
    }
}

// ============================================================
// K3: per (b,c): build Wk[v,k,i] = A[v,i] + b4[c*9+k] + sum_r W4[c*9+k,r]*rel[b,r,v,i]
//     then z[t,i] = sum_{v,k} xs[v][t+k] * Wk[v,k,i]   (xs left-padded by 8 zeros)
// 160 threads: 32 t-tiles (Tt=4) x 5 i-tiles (Ti=5)
// ============================================================
__global__ __launch_bounds__(160) void k3_main(
    const float* __restrict__ x, const float* __restrict__ A,
    const float* __restrict__ W4, const float* __restrict__ b4) {

    int c = blockIdx.x;
    int b = blockIdx.y;
    int tid = threadIdx.x;

    __shared__ __align__(16) float xs[VV][XPAD];     // 13.6 KB
    __shared__ float wk[VV][TSN][VV];                // 22.5 KB
    __shared__ float sW4[TSN*RR];                    // 72
    __shared__ float sb4[TSN];

    // W4 rows for this c (contiguous 72 floats), b4 slice
    if (tid < TSN*RR) sW4[tid] = W4[c*TSN*RR + tid];
    if (tid < TSN)    sb4[tid] = b4[c*TSN + tid];

    // load x tile (transposed to [v][t+8]) + zero left pad
    const float* xp = x + (b*CC + c) * TV;
    for (int i = tid; i < TV; i += 160) {
        int t = i / VV, v = i % VV;
        xs[v][t + TSN - 1] = xp[i];
    }
    for (int i = tid; i < VV*(TSN-1); i += 160) {
        xs[i / (TSN-1)][i % (TSN-1)] = 0.f;
    }
    __syncthreads();

    // build Wk
    for (int it = tid; it < VV*VV; it += 160) {
        int v = it / VV, i = it % VV;
        float rl[RR];
        const float* rp = g_rel + (b*RR*VV + v)*VV + i;
#pragma unroll
        for (int r = 0; r < RR; ++r) rl[r] = rp[r*VV*VV];
        float av = A[v*VV + i];
#pragma unroll
        for (int k = 0; k < TSN; ++k) {
            float s = sb4[k] + av;
#pragma unroll
            for (int r = 0; r < RR; ++r) s += sW4[k*RR + r] * rl[r];
            wk[v][k][i] = s;
        }
    }
    __syncthreads();

    // compute: thread tile 4t x 5i
    int t0 = (tid / 5) * 4;
    int i0 = (tid % 5) * 5;

    float acc[4][5];
#pragma unroll
    for (int a = 0; a < 4; ++a)
#pragma unroll
        for (int j = 0; j < 5; ++j) acc[a][j] = 0.f;

    for (int v = 0; v < VV; ++v) {
        const float4* xv4 = reinterpret_cast<const float4*>(&xs[v][t0]);
        float4 q0 = xv4[0], q1 = xv4[1], q2 = xv4[2];
        float xr[12] = {q0.x,q0.y,q0.z,q0.w, q1.x,q1.y,q1.z,q1.w, q2.x,q2.y,q2.z,q2.w};
#pragma unroll
        for (int k = 0; k < TSN; ++k) {
            float w0 = wk[v][k][i0+0];
            float w1 = wk[v][k][i0+1];
            float w2 = wk[v][k][i0+2];
            float w3 = wk[v][k][i0+3];
            float w4 = wk[v][k][i0+4];
#pragma unroll
            for (int tt = 0; tt < 4; ++tt) {
                float xv = xr[tt + k];
                acc[tt][0] += xv * w0;
                acc[tt][1] += xv * w1;
                acc[tt][2] += xv * w2;
                acc[tt][3] += xv * w3;
                acc[tt][4] += xv * w4;
            }
        }
    }

    float* zp = g_z + (b*CC + c) * TV;
#pragma unroll
    for (int tt = 0; tt < 4; ++tt)
#pragma unroll
        for (int j = 0; j < 5; ++j)
            zp[(t0 + tt)*VV + i0 + j] = acc[tt][j];
}

// ============================================================
// K4: out[b,o,n] = sum_c W3[o,c] * z[b,c,n] + b3[o],  n = t*V+v (3200 per b)
// block: (b, 128-wide n chunk); thread tile 8o x 4n
// ============================================================
__global__ __launch_bounds__(256) void k4_out(
    const float* __restrict__ W3, const float* __restrict__ b3,
    float* __restrict__ out) {

    int nb = blockIdx.x;          // 0..24
    int b  = blockIdx.y;
    int n0 = nb * 128;
    int tid = threadIdx.x;

    __shared__ __align__(16) float zt[CC][128];   // 32 KB
    __shared__ float w3s[OUTC][CC];               // 16 KB  (total = 48 KB exactly)

    const float* zb = g_z + b*CC*TV;
    for (int i = tid; i < CC*128; i += 256) {
        int cidx = i >> 7, n = i & 127;
        zt[cidx][n] = zb[cidx*TV + n0 + n];
    }
    for (int i = tid; i < OUTC*CC; i += 256) {
        ((float*)w3s)[i] = W3[i];
    }
    __syncthreads();

    int o0 = (tid >> 5) * 8;      // 8 o-tiles
    int nl = (tid & 31) * 4;      // 32 n-tiles

    float acc[8][4];
#pragma unroll
    for (int oo = 0; oo < 8; ++oo)
#pragma unroll
        for (int j = 0; j < 4; ++j) acc[oo][j] = 0.f;

    for (int cc = 0; cc < CC; ++cc) {
        float4 zv = *reinterpret_cast<const float4*>(&zt[cc][nl]);
#pragma unroll
        for (int oo = 0; oo < 8; ++oo) {
            float w = w3s[o0 + oo][cc];     // uniform across warp -> broadcast
            acc[oo][0] += w * zv.x;
            acc[oo][1] += w * zv.y;
            acc[oo][2] += w * zv.z;
            acc[oo][3] += w * zv.w;
        }
    }

#pragma unroll
    for (int oo = 0; oo < 8; ++oo) {
        float bias = b3[o0 + oo];
        float4 r;
        r.x = acc[oo][0] + bias;
        r.y = acc[oo][1] + bias;
        r.z = acc[oo][2] + bias;
        r.w = acc[oo][3] + bias;
        *reinterpret_cast<float4*>(&out[(b*OUTC + o0 + oo)*TV + n0 + nl]) = r;
    }
}

// ============================================================
extern "C" void kernel_launch(void* const* d_in, const int* in_sizes, int n_in,
                              void* d_out, int out_size) {
    const float* x  = (const float*)d_in[0];
    const float* A  = (const float*)d_in[1];
    const float* W1 = (const float*)d_in[2];
    const float* b1 = (const float*)d_in[3];
    const float* W2 = (const float*)d_in[4];
    const float* b2 = (const float*)d_in[5];
    const float* W4 = (const float*)d_in[6];
    const float* b4 = (const float*)d_in[7];
    const float* W3 = (const float*)d_in[8];
    const float* b3 = (const float*)d_in[9];
    float* out = (float*)d_out;

    k1_mean<<<BB*CC, 32>>>(x);
    k2_rel<<<BB, 256>>>(W1, b1, W2, b2);
    k3_main<<<dim3(CC, BB), 160>>>(x, A, W4, b4);
    k4_out<<<dim3(TV/128, BB), 256>>>(W3, b3, out);
}

// round 5
// speedup vs baseline: 1.0085x; 1.0085x over previous
#include <cuda_runtime.h>
#include <mma.h>
#include <cstdint>

using namespace nvcuda;

#define BB   64
#define CC   64
#define TT   128
#define VV   25
#define RR   8
#define TSN  9
#define OUTC 64
#define TV   (TT*VV)      // 3200

// ---- device scratch (allocation-free contract) ----
__device__ float g_xm[BB*CC*VV];
__device__ float g_rel[BB*RR*VV*VV];
__device__ float g_z[BB*CC*TV];

__device__ __forceinline__ unsigned smem_u32(const void* p){
    return (unsigned)__cvta_generic_to_shared(p);
}
__device__ __forceinline__ float to_tf32(float f){
    uint32_t u; asm("cvt.rna.tf32.f32 %0, %1;" : "=r"(u) : "f"(f));
    return __uint_as_float(u);
}

// ============================================================
// K1: xm[b,c,v] = mean_t x[b,c,t,v]
// ============================================================
__global__ void k1_mean(const float* __restrict__ x) {
    int bc = blockIdx.x;
    int v  = threadIdx.x;
    if (v >= VV) return;
    const float* p = x + bc * TV + v;
    float acc = 0.f;
#pragma unroll 8
    for (int t = 0; t < TT; ++t) acc += p[t*VV];
    g_xm[bc*VV + v] = acc * (1.0f / TT);
}

// ============================================================
// K2: x1/x2 = W·xm + b ; rel[b,r,v,j] = tanh(x1[r,v] - x2[r,j])
// ============================================================
__global__ void k2_rel(const float* __restrict__ W1, const float* __restrict__ b1,
                       const float* __restrict__ W2, const float* __restrict__ b2) {
    int b   = blockIdx.x;
    int tid = threadIdx.x;
    __shared__ float s_xm[CC*VV];
    __shared__ float s_x1[RR*VV];
    __shared__ float s_x2[RR*VV];

    for (int i = tid; i < CC*VV; i += blockDim.x) s_xm[i] = g_xm[b*CC*VV + i];
    __syncthreads();

    for (int i = tid; i < RR*VV; i += blockDim.x) {
        int r = i / VV, v = i % VV;
        float a1 = b1[r], a2 = b2[r];
#pragma unroll 8
        for (int c = 0; c < CC; ++c) {
            float xv = s_xm[c*VV + v];
            a1 += W1[r*CC + c] * xv;
            a2 += W2[r*CC + c] * xv;
        }
        s_x1[i] = a1; s_x2[i] = a2;
    }
    __syncthreads();

    for (int i = tid; i < RR*VV*VV; i += blockDim.x) {
        int r   = i / (VV*VV);
        int rem = i % (VV*VV);
        int v   = rem / VV;
        int j   = rem % VV;
        g_rel[b*RR*VV*VV + i] = tanhf(s_x1[r*VV + v] - s_x2[r*VV + j]);
    }
}

// ============================================================
// K3: tf32 wmma (m16n16k8) GEMM per (b,c) tile.
//   A_im2col[t][kk=tap*32+v] = xs[t+tap][v]  -> read in place from xs (tap = row shift)
//   B[kk][i]                 = Wk[v][i][tap]
//   z[t][i] = sum_kk A[t][kk]*B[kk][i],  K=288 -> 36 k-chunks of 8
// smem: xs[136][36] floats (19584 B) | Bs[288][36] floats (41472 B)
// 4 warps; warp w owns rows [32w, 32w+32): 2 M-tiles x 2 N-tiles
// ============================================================
#define XSTR 36
#define XS_WORDS (136*XSTR)          // 4896
#define BS_WORDS (288*XSTR)          // 10368
#define SM3_BYTES ((XS_WORDS + BS_WORDS)*4)   // 61056

__global__ __launch_bounds__(128, 1) void k3_wmma(
    const float* __restrict__ x, const float* __restrict__ Astat,
    const float* __restrict__ W4, const float* __restrict__ b4)
{
    extern __shared__ __align__(16) float sm[];
    float* xs = sm;                // [136][36]
    float* Bs = sm + XS_WORDS;     // [288][36]

    int c = blockIdx.x, b = blockIdx.y;
    int tid = threadIdx.x, wid = tid >> 5;

    // zero both tiles (pads must be finite-zero)
    for (int i = tid; i < XS_WORDS; i += 128) xs[i] = 0.f;
    for (int i = tid; i < BS_WORDS; i += 128) Bs[i] = 0.f;
    __syncthreads();

    // stage x -> tf32 xs[t+8][v]
    const float* xp = x + (b*CC + c) * TV;
    for (int i = tid; i < TV; i += 128) {
        int t = i / VV, v = i - t*VV;
        xs[(t + 8)*XSTR + v] = to_tf32(xp[i]);
    }

    // build B[kk=k*32+v][i] = A[v,i] + b4[c*9+k] + sum_r W4[c*9+k,r]*rel[b,r,v,i]
    const float* relp = g_rel + b*RR*VV*VV;
    for (int p = tid; p < VV*VV; p += 128) {
        int v = p / VV, i = p - v*VV;
        float rl[RR];
#pragma unroll
        for (int r = 0; r < RR; ++r) rl[r] = __ldg(relp + r*VV*VV + v*VV + i);
        float av = __ldg(Astat + v*VV + i);
#pragma unroll
        for (int k = 0; k < TSN; ++k) {
            int o = c*TSN + k;
            float s = __ldg(b4 + o) + av;
#pragma unroll
            for (int r = 0; r < RR; ++r) s += __ldg(W4 + o*RR + r) * rl[r];
            Bs[(k*32 + v)*XSTR + i] = to_tf32(s);
        }
    }
    __syncthreads();

    // ---- mainloop ----
    wmma::fragment<wmma::accumulator, 16, 16, 8, float> c00, c01, c10, c11;
    wmma::fill_fragment(c00, 0.f); wmma::fill_fragment(c01, 0.f);
    wmma::fill_fragment(c10, 0.f); wmma::fill_fragment(c11, 0.f);

    int m0 = wid * 32;
#pragma unroll
    for (int q = 0; q < 36; ++q) {
        int tap = q >> 2;
        int vc  = (q & 3) * 8;
        wmma::fragment<wmma::matrix_a, 16, 16, 8, wmma::precision::tf32, wmma::row_major> a0, a1;
        wmma::fragment<wmma::matrix_b, 16, 16, 8, wmma::precision::tf32, wmma::row_major> b0, b1;
        wmma::load_matrix_sync(a0, &xs[(m0 + tap)*XSTR + vc], XSTR);
        wmma::load_matrix_sync(a1, &xs[(m0 + 16 + tap)*XSTR + vc], XSTR);
        wmma::load_matrix_sync(b0, &Bs[q*8*XSTR + 0], XSTR);
        wmma::load_matrix_sync(b1, &Bs[q*8*XSTR + 16], XSTR);
        wmma::mma_sync(c00, a0, b0, c00);
        wmma::mma_sync(c01, a0, b1, c01);
        wmma::mma_sync(c10, a1, b0, c10);
        wmma::mma_sync(c11, a1, b1, c11);
    }
    __syncthreads();            // done reading xs; reuse as z staging [128][32]

    float* zs = sm;
    wmma::store_matrix_sync(&zs[(m0     )*32 +  0], c00, 32, wmma::mem_row_major);
    wmma::store_matrix_sync(&zs[(m0     )*32 + 16], c01, 32, wmma::mem_row_major);
    wmma::store_matrix_sync(&zs[(m0 + 16)*32 +  0], c10, 32, wmma::mem_row_major);
    wmma::store_matrix_sync(&zs[(m0 + 16)*32 + 16], c11, 32, wmma::mem_row_major);
    __syncthreads();

    float* zp = g_z + (b*CC + c) * TV;
    for (int i = tid; i < TV; i += 128) {
        int t = i / VV, ii = i - t*VV;
        zp[i] = zs[t*32 + ii];
    }
}

// ============================================================
// K4: out[b,o,n] = sum_c W3[o,c]*z[b,c,n] + b3[o]; packed f32x2 along o-pairs
// ============================================================
__global__ __launch_bounds__(256) void k4_out(
    const float* __restrict__ W3, const float* __restrict__ b3,
    float* __restrict__ out)
{
    int nb = blockIdx.x, b = blockIdx.y;
    int n0 = nb * 128, tid = threadIdx.x;
    __shared__ __align__(16) float zt[CC][128];     // 32 KB
    __shared__ __align__(16) float w3t[CC][OUTC];   // 16 KB (transposed: [c][o])

    const float* zb = g_z + b*CC*TV;
    for (int i = tid; i < CC*128; i += 256) {
        int cidx = i >> 7, n = i & 127;
        zt[cidx][n] = zb[cidx*TV + n0 + n];
    }
    for (int i = tid; i < OUTC*CC; i += 256) {
        int o = i >> 6, cidx = i & 63;
        w3t[cidx][o] = W3[o*CC + cidx];
    }
    __syncthreads();

    int o0 = (tid >> 5) * 8;
    int nl = (tid & 31) * 4;

    unsigned long long acc[4][4];   // [o-pair][n]
#pragma unroll
    for (int p = 0; p < 4; ++p)
#pragma unroll
        for (int n = 0; n < 4; ++n) acc[p][n] = 0ull;

    unsigned waddr = smem_u32(&w3t[0][o0]);
    for (int cc2 = 0; cc2 < CC; ++cc2) {
        float4 zv = *(const float4*)(&zt[cc2][nl]);
        unsigned long long zz[4];
        asm("mov.b64 %0,{%1,%1};" : "=l"(zz[0]) : "r"(__float_as_uint(zv.x)));
        asm("mov.b64 %0,{%1,%1};" : "=l"(zz[1]) : "r"(__float_as_uint(zv.y)));
        asm("mov.b64 %0,{%1,%1};" : "=l"(zz[2]) : "r"(__float_as_uint(zv.z)));
        asm("mov.b64 %0,{%1,%1};" : "=l"(zz[3]) : "r"(__float_as_uint(zv.w)));
        unsigned long long w01, w23, w45, w67;
        asm("ld.shared.v2.b64 {%0,%1},[%2];" : "=l"(w01), "=l"(w23) : "r"(waddr + cc2*OUTC*4));
        asm("ld.shared.v2.b64 {%0,%1},[%2];" : "=l"(w45), "=l"(w67) : "r"(waddr + cc2*OUTC*4 + 16));
#pragma unroll
        for (int n = 0; n < 4; ++n) {
            asm("fma.rn.f32x2 %0,%1,%2,%0;" : "+l"(acc[0][n]) : "l"(w01), "l"(zz[n]));
            asm("fma.rn.f32x2 %0,%1,%2,%0;" : "+l"(acc[1][n]) : "l"(w23), "l"(zz[n]));
            asm("fma.rn.f32x2 %0,%1,%2,%0;" : "+l"(acc[2][n]) : "l"(w45), "l"(zz[n]));
            asm("fma.rn.f32x2 %0,%1,%2,%0;" : "+l"(acc[3][n]) : "l"(w67), "l"(zz[n]));
        }
    }

#pragma unroll
    for (int p = 0; p < 4; ++p) {
        float lo[4], hi[4];
#pragma unroll
        for (int n = 0; n < 4; ++n) {
            unsigned ulo, uhi;
            asm("mov.b64 {%0,%1},%2;" : "=r"(ulo), "=r"(uhi) : "l"(acc[p][n]));
            lo[n] = __uint_as_float(ulo);
            hi[n] = __uint_as_float(uhi);
        }
        int oe = o0 + 2*p, oo2 = oe + 1;
        float be = b3[oe], bo = b3[oo2];
        float4 re = { lo[0]+be, lo[1]+be, lo[2]+be, lo[3]+be };
        float4 ro = { hi[0]+bo, hi[1]+bo, hi[2]+bo, hi[3]+bo };
        *(float4*)&out[((size_t)b*OUTC + oe )*TV + n0 + nl] = re;
        *(float4*)&out[((size_t)b*OUTC + oo2)*TV + n0 + nl] = ro;
    }
}

// ============================================================
extern "C" void kernel_launch(void* const* d_in, const int* in_sizes, int n_in,
                              void* d_out, int out_size) {
    const float* x  = (const float*)d_in[0];
    const float* A  = (const float*)d_in[1];
    const float* W1 = (const float*)d_in[2];
    const float* b1 = (const float*)d_in[3];
    const float* W2 = (const float*)d_in[4];
    const float* b2 = (const float*)d_in[5];
    const float* W4 = (const float*)d_in[6];
    const float* b4 = (const float*)d_in[7];
    const float* W3 = (const float*)d_in[8];
    const float* b3 = (const float*)d_in[9];
    float* out = (float*)d_out;

    static bool attr_set = false;
    if (!attr_set) {
        cudaFuncSetAttribute(k3_wmma, cudaFuncAttributeMaxDynamicSharedMemorySize, SM3_BYTES);
        attr_set = true;
    }

    k1_mean<<<BB*CC, 32>>>(x);
    k2_rel<<<BB, 256>>>(W1, b1, W2, b2);
    k3_wmma<<<dim3(CC, BB), 128, SM3_BYTES>>>(x, A, W4, b4);
    k4_out<<<dim3(TV/128, BB), 256>>>(W3, b3, out);
}